// round 1
// baseline (speedup 1.0000x reference)
#include <cuda_runtime.h>
#include <math.h>

// Problem constants (fixed shapes for MWTLayer1d_9663676416254)
#define Pn 8
#define Bn 8
#define Cn 128
#define Ln 8192
#define LS 4096       // Ls = L/2
#define PC 1024       // P*C
#define NSTAT 32768.f // B * Ls

// Scratch: sc coefficients and mixed coefficients, layout [B][PC][Ls]
__device__ float g_sc[(size_t)Bn * PC * LS];
__device__ float g_mix[(size_t)Bn * PC * LS];
__device__ float g_mean[PC];
__device__ float g_rstd[PC];

// ---------------------------------------------------------------------------
// Pass 1: analysis. Reads xs [P,B,C,L]. Produces:
//   - sc scratch [B][p*C+c][Ls]   (scaling coeffs, GEMM-friendly layout)
//   - out[..., 4096:8192]         (detail half of synthesis, done directly)
// One thread handles 4 consecutive x values (float4) -> 2 sc, 2 det, 2 out.
// ---------------------------------------------------------------------------
__global__ __launch_bounds__(256) void prep_kernel(
    const float4* __restrict__ xs4, const float* __restrict__ A,
    const float* __restrict__ S, float* __restrict__ out,
    float* __restrict__ sc)
{
    long tid = (long)blockIdx.x * blockDim.x + threadIdx.x; // 8192 rows * 2048 n
    int n   = (int)(tid & 2047);
    int row = (int)(tid >> 11);              // row = (p*B+b)*C + c  in [0,8192)

    float4 x = xs4[(long)row * 2048 + n];    // x[4n .. 4n+3]

    float a00 = A[0], a01 = A[1], a10 = A[2], a11 = A[3];
    float s00 = S[0], s01 = S[1], s10 = S[2], s11 = S[3];

    float sc0 = a00 * x.x + a01 * x.y;       // sc[2n]
    float sc1 = a00 * x.z + a01 * x.w;       // sc[2n+1]
    float d0  = a10 * x.x + a11 * x.y;       // det[2n]
    float d1  = a10 * x.z + a11 * x.w;       // det[2n+1]

    // Synthesis of detail half: out[l = 4096 + 2n + m] = S[m,0]*det[2n] + S[m,1]*det[2n+1]
    float2 yo = make_float2(s00 * d0 + s01 * d1, s10 * d0 + s11 * d1);
    *(float2*)(out + (long)row * Ln + LS + 2 * n) = yo;

    int p = row >> 10;
    int b = (row >> 7) & 7;
    int c = row & 127;
    long scoff = ((long)b * PC + p * Cn + c) * LS + 2 * n;
    *(float2*)(sc + scoff) = make_float2(sc0, sc1);
}

// ---------------------------------------------------------------------------
// Pass 2: per-batch SGEMM  mix[b] = W(1024x1024, row-major) @ sc[b](1024x4096)
// Classic 128x128x8 blocktile, 8x8 microtile, 256 threads.
// ---------------------------------------------------------------------------
#define BM 128
#define BNn 128
#define BK 8
#define TM 8
#define TN 8

__global__ __launch_bounds__(256) void gemm_kernel(
    const float* __restrict__ W, const float* __restrict__ X,
    float* __restrict__ Y)
{
    int b  = blockIdx.z;
    const float* Xb = X + (long)b * PC * LS;
    float*       Yb = Y + (long)b * PC * LS;
    int m0 = blockIdx.y * BM;
    int n0 = blockIdx.x * BNn;

    __shared__ float As[BK][BM];   // transposed: As[k][m]
    __shared__ float Bs[BK][BNn];

    int tid = threadIdx.x;
    int aRow = tid >> 1;           // 0..127
    int aCol = (tid & 1) * 4;      // 0 or 4
    int bRow = tid >> 5;           // 0..7
    int bCol = (tid & 31) * 4;     // 0..124
    int tx = tid & 15;
    int ty = tid >> 4;

    float acc[TM][TN];
#pragma unroll
    for (int i = 0; i < TM; i++)
#pragma unroll
        for (int j = 0; j < TN; j++) acc[i][j] = 0.f;

    for (int k0 = 0; k0 < PC; k0 += BK) {
        float4 av = *(const float4*)(W + (long)(m0 + aRow) * PC + k0 + aCol);
        As[aCol + 0][aRow] = av.x;
        As[aCol + 1][aRow] = av.y;
        As[aCol + 2][aRow] = av.z;
        As[aCol + 3][aRow] = av.w;
        float4 bv = *(const float4*)(Xb + (long)(k0 + bRow) * LS + n0 + bCol);
        *(float4*)&Bs[bRow][bCol] = bv;
        __syncthreads();

#pragma unroll
        for (int kk = 0; kk < BK; kk++) {
            float rm[TM], rn[TN];
#pragma unroll
            for (int i = 0; i < TM; i++) rm[i] = As[kk][ty * TM + i];
#pragma unroll
            for (int j = 0; j < TN; j++) rn[j] = Bs[kk][tx * TN + j];
#pragma unroll
            for (int i = 0; i < TM; i++)
#pragma unroll
                for (int j = 0; j < TN; j++) acc[i][j] += rm[i] * rn[j];
        }
        __syncthreads();
    }

#pragma unroll
    for (int i = 0; i < TM; i++) {
        int m = m0 + ty * TM + i;
#pragma unroll
        for (int j = 0; j < TN; j += 4) {
            *(float4*)(Yb + (long)m * LS + n0 + tx * TN + j) =
                make_float4(acc[i][j], acc[i][j + 1], acc[i][j + 2], acc[i][j + 3]);
        }
    }
}

// ---------------------------------------------------------------------------
// Pass 3: BatchNorm statistics per channel (biased var over B,Ls = 32768 vals)
// One block (256 threads) per channel.
// ---------------------------------------------------------------------------
__global__ __launch_bounds__(256) void bn_stats_kernel(
    const float* __restrict__ Y, float* __restrict__ mean,
    float* __restrict__ rstd)
{
    int i = blockIdx.x;  // channel 0..1023
    float s = 0.f, ss = 0.f;
    const float* base = Y + (long)i * LS;
    for (int b = 0; b < Bn; b++) {
        const float* row = base + (long)b * PC * LS;
        for (int l = threadIdx.x * 4; l < LS; l += blockDim.x * 4) {
            float4 v = *(const float4*)(row + l);
            s  += v.x + v.y + v.z + v.w;
            ss += v.x * v.x + v.y * v.y + v.z * v.z + v.w * v.w;
        }
    }
    __shared__ float shs[8], shss[8];
#pragma unroll
    for (int o = 16; o > 0; o >>= 1) {
        s  += __shfl_down_sync(0xffffffffu, s, o);
        ss += __shfl_down_sync(0xffffffffu, ss, o);
    }
    if ((threadIdx.x & 31) == 0) {
        shs[threadIdx.x >> 5]  = s;
        shss[threadIdx.x >> 5] = ss;
    }
    __syncthreads();
    if (threadIdx.x < 8) {
        s  = shs[threadIdx.x];
        ss = shss[threadIdx.x];
#pragma unroll
        for (int o = 4; o > 0; o >>= 1) {
            s  += __shfl_down_sync(0xffu, s, o);
            ss += __shfl_down_sync(0xffu, ss, o);
        }
        if (threadIdx.x == 0) {
            float m = s / NSTAT;
            mean[i] = m;
            rstd[i] = rsqrtf(ss / NSTAT - m * m + 1e-5f);
        }
    }
}

// ---------------------------------------------------------------------------
// Pass 4: normalize + exact GELU + synthesis of scaling half -> out[..., :4096]
// ---------------------------------------------------------------------------
__global__ __launch_bounds__(256) void final_kernel(
    const float* __restrict__ Y, const float* __restrict__ mean,
    const float* __restrict__ rstd, const float* __restrict__ gamma,
    const float* __restrict__ beta, const float* __restrict__ S,
    float* __restrict__ out)
{
    long tid = (long)blockIdx.x * blockDim.x + threadIdx.x; // B*PC rows * 2048 n
    int n  = (int)(tid & 2047);
    int rj = (int)(tid >> 11);        // rj = b*1024 + j
    int b  = rj >> 10;
    int j  = rj & 1023;

    float2 v = *(const float2*)(Y + (long)rj * LS + 2 * n);
    float mu = mean[j], rs = rstd[j], ga = gamma[j], be = beta[j];

    float h0 = (v.x - mu) * rs * ga + be;
    float h1 = (v.y - mu) * rs * ga + be;
    const float inv_sqrt2 = 0.70710678118654752f;
    float g0 = 0.5f * h0 * (1.f + erff(h0 * inv_sqrt2));
    float g1 = 0.5f * h1 * (1.f + erff(h1 * inv_sqrt2));

    float s00 = S[0], s01 = S[1], s10 = S[2], s11 = S[3];
    int p = j >> 7;
    int c = j & 127;
    long ooff = (((long)p * Bn + b) * Cn + c) * Ln + 2 * n;
    *(float2*)(out + ooff) = make_float2(s00 * g0 + s01 * g1, s10 * g0 + s11 * g1);
}

// ---------------------------------------------------------------------------
extern "C" void kernel_launch(void* const* d_in, const int* in_sizes, int n_in,
                              void* d_out, int out_size)
{
    const float* xs    = (const float*)d_in[0];
    const float* A     = (const float*)d_in[1];
    const float* S     = (const float*)d_in[2];
    const float* Wc    = (const float*)d_in[3];
    const float* gamma = (const float*)d_in[4];
    const float* beta  = (const float*)d_in[5];
    float* out = (float*)d_out;

    float* sc;   cudaGetSymbolAddress((void**)&sc,   g_sc);
    float* mix;  cudaGetSymbolAddress((void**)&mix,  g_mix);
    float* mean; cudaGetSymbolAddress((void**)&mean, g_mean);
    float* rstd; cudaGetSymbolAddress((void**)&rstd, g_rstd);

    // Pass 1: analysis + detail-half synthesis (65536 blocks x 256)
    prep_kernel<<<65536, 256>>>((const float4*)xs, A, S, out, sc);

    // Pass 2: 8x GEMM 1024x4096x1024
    dim3 ggrid(LS / BNn, PC / BM, Bn); // (32, 8, 8)
    gemm_kernel<<<ggrid, 256>>>(Wc, sc, mix);

    // Pass 3: BN statistics
    bn_stats_kernel<<<PC, 256>>>(mix, mean, rstd);

    // Pass 4: BN + GELU + scaling-half synthesis
    final_kernel<<<65536, 256>>>(mix, mean, rstd, gamma, beta, S, out);
}

// round 4
// speedup vs baseline: 2.1516x; 2.1516x over previous
#include <cuda_runtime.h>
#include <cuda_bf16.h>
#include <cstdint>
#include <math.h>

// Fixed shapes: P=8, B=8, C=128, L=8192, k=2
#define Bn 8
#define PC 1024
#define LS 4096
#define Ln 8192
#define NSTAT 32768.f
#define NTOT 32768      // B * LS, flattened GEMM N

// ---------------- scratch (device globals; no runtime alloc) ---------------
__device__ __nv_bfloat16 g_whi[1024 * 1024];
__device__ __nv_bfloat16 g_wlo[1024 * 1024];
__device__ __nv_bfloat16 g_xhi[(size_t)NTOT * PC];  // X^T hi: [b*Ls + n][k]
__device__ __nv_bfloat16 g_xlo[(size_t)NTOT * PC];  // X^T lo
__device__ float g_mix[(size_t)Bn * PC * LS];
__device__ float g_mean[PC];
__device__ float g_rstd[PC];

// ---------------- helpers ---------------------------------------------------
__device__ __forceinline__ uint32_t smem_u32(const void* p) {
    uint32_t a;
    asm("{ .reg .u64 t; cvta.to.shared.u64 t, %1; cvt.u32.u64 %0, t; }"
        : "=r"(a) : "l"(p));
    return a;
}
#define CP16(s, g) asm volatile("cp.async.cg.shared.global [%0], [%1], 16;" :: "r"(s), "l"(g))
#define CP_COMMIT() asm volatile("cp.async.commit_group;" ::: "memory")
#define CP_WAIT1()  asm volatile("cp.async.wait_group 1;" ::: "memory")

#define LDSM4(r0, r1, r2, r3, a)                                              \
    asm volatile("ldmatrix.sync.aligned.m8n8.x4.shared.b16 {%0,%1,%2,%3}, [%4];" \
                 : "=r"(r0), "=r"(r1), "=r"(r2), "=r"(r3) : "r"(a))

#define MMA16816(c, a, b)                                                     \
    asm volatile("mma.sync.aligned.m16n8k16.row.col.f32.bf16.bf16.f32 "       \
                 "{%0,%1,%2,%3}, {%4,%5,%6,%7}, {%8,%9}, {%0,%1,%2,%3};"      \
                 : "+f"((c)[0]), "+f"((c)[1]), "+f"((c)[2]), "+f"((c)[3])     \
                 : "r"((a)[0]), "r"((a)[1]), "r"((a)[2]), "r"((a)[3]),        \
                   "r"((b)[0]), "r"((b)[1]))

// swizzled byte offset inside a 128x32 bf16 tile (64B rows, ldmatrix-safe)
__device__ __forceinline__ uint32_t swz(int r, int c) {
    return (uint32_t)(r * 64 + ((c ^ ((r >> 1) & 3)) << 4));
}

// ---------------------------------------------------------------------------
// W split: fp32 -> (hi, lo) bf16
// ---------------------------------------------------------------------------
__global__ __launch_bounds__(256) void wconv_kernel(
    const float* __restrict__ W, __nv_bfloat16* __restrict__ hi,
    __nv_bfloat16* __restrict__ lo)
{
    int i = blockIdx.x * 256 + threadIdx.x;
    float w = W[i];
    __nv_bfloat16 h = __float2bfloat16_rn(w);
    hi[i] = h;
    lo[i] = __float2bfloat16_rn(w - __bfloat162float(h));
}

// ---------------------------------------------------------------------------
// Pass 1: Haar analysis. Writes out[...,4096:] (detail synthesis, exact fp32)
// and X^T hi/lo bf16 in [b*Ls+n][k] layout for the GEMM B operand.
// ---------------------------------------------------------------------------
__global__ __launch_bounds__(256) void prep_kernel(
    const float4* __restrict__ xs4, const float* __restrict__ A,
    const float* __restrict__ S, float* __restrict__ out,
    __nv_bfloat16* __restrict__ xhi, __nv_bfloat16* __restrict__ xlo)
{
    __shared__ __nv_bfloat16 shi[64][66], slo[64][66];
    int b = blockIdx.z, kt = blockIdx.y, nt = blockIdx.x;
    int k0 = kt * 64, n0 = nt * 64;
    int p = k0 >> 7, c0 = k0 & 127;
    int tid = threadIdx.x;
    int txn = tid & 31, tyc = tid >> 5;

    float a00 = A[0], a01 = A[1], a10 = A[2], a11 = A[3];
    float s00 = S[0], s01 = S[1], s10 = S[2], s11 = S[3];
    int nloc = 2 * txn;

#pragma unroll
    for (int r = 0; r < 8; r++) {
        int cl = tyc * 8 + r;
        long rowx = (long)((p * 8 + b) * 128 + c0 + cl);
        float4 x = xs4[rowx * 2048 + (n0 >> 1) + txn];
        float sc0 = a00 * x.x + a01 * x.y, sc1 = a00 * x.z + a01 * x.w;
        float d0  = a10 * x.x + a11 * x.y, d1  = a10 * x.z + a11 * x.w;
        *(float2*)(out + rowx * Ln + LS + n0 + nloc) =
            make_float2(s00 * d0 + s01 * d1, s10 * d0 + s11 * d1);
        __nv_bfloat16 h0 = __float2bfloat16_rn(sc0);
        __nv_bfloat16 h1 = __float2bfloat16_rn(sc1);
        shi[nloc][cl] = h0;  shi[nloc + 1][cl] = h1;
        slo[nloc][cl]     = __float2bfloat16_rn(sc0 - __bfloat162float(h0));
        slo[nloc + 1][cl] = __float2bfloat16_rn(sc1 - __bfloat162float(h1));
    }
    __syncthreads();
    int kk = tid & 63, ny = tid >> 6;
#pragma unroll
    for (int w = 0; w < 16; w++) {
        int nl = ny * 16 + w;
        long off = ((long)b * LS + n0 + nl) * 1024 + k0 + kk;
        xhi[off] = shi[nl][kk];
        xlo[off] = slo[nl][kk];
    }
}

// ---------------------------------------------------------------------------
// Pass 2: bf16 HMMA GEMM with 3-term hi/lo split.
//   Y[m][n] = Whi@Xhi + Whi@Xlo + Wlo@Xhi   (fp32 accum)
// M=1024, N=32768 (flattened over b), K=1024.
// CTA tile 128x128x32, 3-stage cp.async, 8 warps (2x4), warp tile 64x32.
// ---------------------------------------------------------------------------
#define GBK 32
#define KTILES 32          // 1024 / GBK
#define TILE_B 8192        // 128 rows * 64 bytes
#define STG_B (4 * TILE_B) // Ah, Al, Bh, Bl
#define GSTG 3
#define GEMM_SMEM (GSTG * STG_B)

__device__ __forceinline__ void g_load_stage(
    uint32_t sb, int tid, int k0,
    const __nv_bfloat16* gAh, const __nv_bfloat16* gAl,
    const __nv_bfloat16* gBh, const __nv_bfloat16* gBl)
{
    // 512 16B-chunks per 128x32 tile; 2 per thread per tile
#pragma unroll
    for (int t = 0; t < 2; t++) {
        int ch = tid * 2 + t;
        int r = ch >> 2, c = ch & 3;
        uint32_t so = swz(r, c);
        long go = (long)r * 1024 + k0 + c * 8;
        CP16(sb + so,              gAh + go);
        CP16(sb + TILE_B + so,     gAl + go);
        CP16(sb + 2 * TILE_B + so, gBh + go);
        CP16(sb + 3 * TILE_B + so, gBl + go);
    }
    CP_COMMIT();
}

__global__ __launch_bounds__(256, 1) void gemm_hmma_kernel(
    const __nv_bfloat16* __restrict__ Whi, const __nv_bfloat16* __restrict__ Wlo,
    const __nv_bfloat16* __restrict__ Xhi, const __nv_bfloat16* __restrict__ Xlo,
    float* __restrict__ Y)
{
    extern __shared__ char smem[];
    uint32_t sbase = smem_u32(smem);
    int tid = threadIdx.x;
    int lane = tid & 31, wid = tid >> 5;
    int wm = wid & 1, wn = wid >> 1;        // 2 x 4 warp grid
    int m0 = blockIdx.y * 128;
    long n0g = (long)blockIdx.x * 128;

    const __nv_bfloat16* gAh = Whi + (long)m0 * 1024;
    const __nv_bfloat16* gAl = Wlo + (long)m0 * 1024;
    const __nv_bfloat16* gBh = Xhi + n0g * 1024;
    const __nv_bfloat16* gBl = Xlo + n0g * 1024;

    float acc[4][4][4];
#pragma unroll
    for (int i = 0; i < 4; i++)
#pragma unroll
        for (int j = 0; j < 4; j++)
#pragma unroll
            for (int q = 0; q < 4; q++) acc[i][j][q] = 0.f;

    // prologue: stages 0,1
    g_load_stage(sbase, tid, 0, gAh, gAl, gBh, gBl);
    g_load_stage(sbase + STG_B, tid, GBK, gAh, gAl, gBh, gBl);

    // per-lane ldmatrix address pieces
    int a_row = (lane & 15);          // + wm*64 + mt*16
    int a_kg  = lane >> 4;            // 0/1 -> +8 k
    int b_row = (lane & 7);           // + wn*32 + nt*16 + (g>>1)*8
    int b_g   = lane >> 3;

    for (int ks = 0; ks < KTILES; ks++) {
        CP_WAIT1();
        __syncthreads();
        // issue next stage (overwrites the stage finished last iteration)
        if (ks + GSTG - 1 < KTILES)
            g_load_stage(sbase + ((ks + GSTG - 1) % GSTG) * STG_B, tid,
                         (ks + GSTG - 1) * GBK, gAh, gAl, gBh, gBl);
        else
            CP_COMMIT();

        uint32_t st = sbase + (ks % GSTG) * STG_B;
        uint32_t sAh = st, sAl = st + TILE_B;
        uint32_t sBh = st + 2 * TILE_B, sBl = st + 3 * TILE_B;

#pragma unroll
        for (int kk2 = 0; kk2 < 2; kk2++) {
            uint32_t ah[4][4], al[4][4], bh[2][4], bl[2][4];
#pragma unroll
            for (int mt = 0; mt < 4; mt++) {
                int r = wm * 64 + mt * 16 + a_row;
                int c = kk2 * 2 + a_kg;
                uint32_t o = swz(r, c);
                LDSM4(ah[mt][0], ah[mt][1], ah[mt][2], ah[mt][3], sAh + o);
                LDSM4(al[mt][0], al[mt][1], al[mt][2], al[mt][3], sAl + o);
            }
#pragma unroll
            for (int nt = 0; nt < 2; nt++) {
                int r = wn * 32 + nt * 16 + (b_g >> 1) * 8 + b_row;
                int c = kk2 * 2 + (b_g & 1);
                uint32_t o = swz(r, c);
                LDSM4(bh[nt][0], bh[nt][1], bh[nt][2], bh[nt][3], sBh + o);
                LDSM4(bl[nt][0], bl[nt][1], bl[nt][2], bl[nt][3], sBl + o);
            }
#pragma unroll
            for (int mt = 0; mt < 4; mt++) {
#pragma unroll
                for (int n8 = 0; n8 < 4; n8++) {
                    uint32_t bfh[2] = { bh[n8 >> 1][(n8 & 1) * 2],
                                        bh[n8 >> 1][(n8 & 1) * 2 + 1] };
                    uint32_t bfl[2] = { bl[n8 >> 1][(n8 & 1) * 2],
                                        bl[n8 >> 1][(n8 & 1) * 2 + 1] };
                    MMA16816(acc[mt][n8], ah[mt], bfh);
                    MMA16816(acc[mt][n8], ah[mt], bfl);
                    MMA16816(acc[mt][n8], al[mt], bfh);
                }
            }
        }
        __syncthreads();
    }

    // epilogue: write to mix[b][m][ls]; whole CTA is within one b
    int bb = (int)(n0g >> 12);
    int ncol0 = (int)(n0g & 4095) + wn * 32;
    float* ybase = Y + (long)bb * PC * LS;
#pragma unroll
    for (int mt = 0; mt < 4; mt++) {
        int mrow = m0 + wm * 64 + mt * 16 + (lane >> 2);
#pragma unroll
        for (int n8 = 0; n8 < 4; n8++) {
            int col = ncol0 + n8 * 8 + (lane & 3) * 2;
            *(float2*)(ybase + (long)mrow * LS + col) =
                make_float2(acc[mt][n8][0], acc[mt][n8][1]);
            *(float2*)(ybase + (long)(mrow + 8) * LS + col) =
                make_float2(acc[mt][n8][2], acc[mt][n8][3]);
        }
    }
}

// ---------------------------------------------------------------------------
// Pass 3: BatchNorm stats per channel (biased, over B*Ls = 32768 values)
// ---------------------------------------------------------------------------
__global__ __launch_bounds__(256) void bn_stats_kernel(
    const float* __restrict__ Y, float* __restrict__ mean,
    float* __restrict__ rstd)
{
    int i = blockIdx.x;
    float s = 0.f, ss = 0.f;
    const float* base = Y + (long)i * LS;
    for (int b = 0; b < Bn; b++) {
        const float* row = base + (long)b * PC * LS;
        for (int l = threadIdx.x * 4; l < LS; l += blockDim.x * 4) {
            float4 v = *(const float4*)(row + l);
            s  += v.x + v.y + v.z + v.w;
            ss += v.x * v.x + v.y * v.y + v.z * v.z + v.w * v.w;
        }
    }
    __shared__ float shs[8], shss[8];
#pragma unroll
    for (int o = 16; o > 0; o >>= 1) {
        s  += __shfl_down_sync(0xffffffffu, s, o);
        ss += __shfl_down_sync(0xffffffffu, ss, o);
    }
    if ((threadIdx.x & 31) == 0) { shs[threadIdx.x >> 5] = s; shss[threadIdx.x >> 5] = ss; }
    __syncthreads();
    if (threadIdx.x < 8) {
        s = shs[threadIdx.x]; ss = shss[threadIdx.x];
#pragma unroll
        for (int o = 4; o > 0; o >>= 1) {
            s  += __shfl_down_sync(0xffu, s, o);
            ss += __shfl_down_sync(0xffu, ss, o);
        }
        if (threadIdx.x == 0) {
            float m = s / NSTAT;
            mean[i] = m;
            rstd[i] = rsqrtf(ss / NSTAT - m * m + 1e-5f);
        }
    }
}

// ---------------------------------------------------------------------------
// Pass 4: BN + exact GELU + scaling-half synthesis -> out[..., :4096]
// ---------------------------------------------------------------------------
__global__ __launch_bounds__(256) void final_kernel(
    const float* __restrict__ Y, const float* __restrict__ mean,
    const float* __restrict__ rstd, const float* __restrict__ gamma,
    const float* __restrict__ beta, const float* __restrict__ S,
    float* __restrict__ out)
{
    long tid = (long)blockIdx.x * blockDim.x + threadIdx.x;
    int n  = (int)(tid & 2047);
    int rj = (int)(tid >> 11);
    int b  = rj >> 10;
    int j  = rj & 1023;

    float2 v = *(const float2*)(Y + (long)rj * LS + 2 * n);
    float mu = mean[j], rs = rstd[j], ga = gamma[j], be = beta[j];
    float h0 = (v.x - mu) * rs * ga + be;
    float h1 = (v.y - mu) * rs * ga + be;
    const float inv_sqrt2 = 0.70710678118654752f;
    float g0 = 0.5f * h0 * (1.f + erff(h0 * inv_sqrt2));
    float g1 = 0.5f * h1 * (1.f + erff(h1 * inv_sqrt2));

    float s00 = S[0], s01 = S[1], s10 = S[2], s11 = S[3];
    int p = j >> 7, c = j & 127;
    long ooff = (((long)p * Bn + b) * 128 + c) * Ln + 2 * n;
    *(float2*)(out + ooff) = make_float2(s00 * g0 + s01 * g1, s10 * g0 + s11 * g1);
}

// ---------------------------------------------------------------------------
extern "C" void kernel_launch(void* const* d_in, const int* in_sizes, int n_in,
                              void* d_out, int out_size)
{
    const float* xs    = (const float*)d_in[0];
    const float* A     = (const float*)d_in[1];
    const float* S     = (const float*)d_in[2];
    const float* Wc    = (const float*)d_in[3];
    const float* gamma = (const float*)d_in[4];
    const float* beta  = (const float*)d_in[5];
    float* out = (float*)d_out;

    __nv_bfloat16 *whi, *wlo, *xhi, *xlo;
    float *mix, *mean, *rstd;
    cudaGetSymbolAddress((void**)&whi, g_whi);
    cudaGetSymbolAddress((void**)&wlo, g_wlo);
    cudaGetSymbolAddress((void**)&xhi, g_xhi);
    cudaGetSymbolAddress((void**)&xlo, g_xlo);
    cudaGetSymbolAddress((void**)&mix, g_mix);
    cudaGetSymbolAddress((void**)&mean, g_mean);
    cudaGetSymbolAddress((void**)&rstd, g_rstd);

    cudaFuncSetAttribute(gemm_hmma_kernel,
                         cudaFuncAttributeMaxDynamicSharedMemorySize, GEMM_SMEM);

    wconv_kernel<<<4096, 256>>>(Wc, whi, wlo);
    prep_kernel<<<dim3(64, 16, 8), 256>>>((const float4*)xs, A, S, out, xhi, xlo);
    gemm_hmma_kernel<<<dim3(256, 8), 256, GEMM_SMEM>>>(whi, wlo, xhi, xlo, mix);
    bn_stats_kernel<<<PC, 256>>>(mix, mean, rstd);
    final_kernel<<<65536, 256>>>(mix, mean, rstd, gamma, beta, S, out);
}